// round 10
// baseline (speedup 1.0000x reference)
#include <cuda_runtime.h>
#include <cuda_bf16.h>
#include <cstdint>

// Problem constants
#define TT   1024
#define BB   32
#define NH   8
#define DD   32
#define YD   97
#define INDIM 256          // NH*DD
#define ROWSTRIDE 8192     // BB*INDIM

typedef unsigned long long u64;

// -------- scratch (device globals; no allocation allowed) ----------
__device__ float g_fwm[(size_t)TT * BB * INDIM];   // FWM output pre-GEMM, 33.5 MB

// -------- packed f32x2 helpers ----------
__device__ __forceinline__ u64 ffma2(u64 a, u64 b, u64 c) {
    u64 d;
    asm("fma.rn.f32x2 %0, %1, %2, %3;" : "=l"(d) : "l"(a), "l"(b), "l"(c));
    return d;
}
__device__ __forceinline__ u64 add2(u64 a, u64 b) {
    u64 d;
    asm("add.rn.f32x2 %0, %1, %2;" : "=l"(d) : "l"(a), "l"(b));
    return d;
}
__device__ __forceinline__ u64 pack2(float a, float b) {
    u64 r;
    asm("mov.b64 %0, {%1, %2};" : "=l"(r) : "f"(a), "f"(b));
    return r;
}
__device__ __forceinline__ u64 bcast2(float a) {
    u64 r;
    asm("mov.b64 %0, {%1, %1};" : "=l"(r) : "f"(a));
    return r;
}
__device__ __forceinline__ float hsum2(u64 v) {
    float a, b;
    asm("mov.b64 {%0, %1}, %2;" : "=f"(a), "=f"(b) : "l"(v));
    return a + b;
}

// float4 viewed as two packed f32x2
union f4u {
    float4 f;
    u64    u[2];
};
__device__ __forceinline__ f4u ld4(const float* p) {
    f4u r;
    r.f = *(const float4*)p;   // LDS.128
    return r;
}

// -------- warp sum (butterfly; only used by producers, off consumers) ----
__device__ __forceinline__ float wsum(float v) {
#pragma unroll
    for (int o = 16; o; o >>= 1) v += __shfl_xor_sync(0xffffffffu, v, o);
    return v;
}

__device__ __forceinline__ float hsum4(const u64* a) {
    return hsum2(add2(add2(a[0], a[1]), add2(a[2], a[3])));
}

// ======================================================================
// Kernel 1: fused softmax(h) + SRWM + FWM recurrence. One CTA per (b,h).
// Softmaxes published UNNORMALIZED (p = exp(y)) together with r = 1/sum(p);
// consumers fold r algebraically -> all consumer reductions are register
// add/fma trees, no shuffles. One barrier per step.
// ======================================================================
__global__ __launch_bounds__(256, 2)
void srwm_kernel(const float* __restrict__ h,
                 const float* __restrict__ W_y, const float* __restrict__ W_q,
                 const float* __restrict__ W_k, const float* __restrict__ w_b,
                 const float* __restrict__ sW_y, const float* __restrict__ sW_q,
                 const float* __restrict__ sW_k, const float* __restrict__ sw_b,
                 const float* __restrict__ F0) {
    __shared__ __align__(16) float xs[2][DD];                    // p_x
    __shared__ __align__(16) float q_s[2][DD], k_s[2][DD];       // p_q, p_k
    __shared__ __align__(16) float fq_s[2][DD], fk_s[2][DD];     // p_fq, p_fk
    __shared__ __align__(16) float fv_s[2][DD];
    __shared__ __align__(16) float beta_s[2][4];
    __shared__ float fb_s[2];
    __shared__ float rx_s[2], rq_s[2], rk_s[2], rfq_s[2], rfk_s[2];

    const int bh   = blockIdx.x;           // b*NH + h
    const int hh   = bh & (NH - 1);
    const int tid  = threadIdx.x;
    const int warp = tid >> 5;
    const int lane = tid & 31;

    // ---- role / column assignment ----
    // role 0: Wy col e   role 1: wb col e (warp3 lanes>=1, duplicated)
    // role 2: Wq col e   role 3: Wk col e
    // role 4: F col e (warp 6, FWM only)   role 5: x staging (warp 7)
    int role, e;
    if (warp < 3)            { role = 0; e = warp * 32 + lane; }
    else if (warp == 3) {
        if (lane == 0)       { role = 0; e = 96; }
        else                 { role = 1; e = (lane - 1) & 3; }
    }
    else if (warp == 4)      { role = 2; e = lane; }
    else if (warp == 5)      { role = 3; e = lane; }
    else if (warp == 6)      { role = 4; e = lane; }
    else                     { role = 5; e = lane; }

    const int bidx = (role == 0) ? 0 : (role == 2) ? 1 : (role == 3) ? 2 : 3;

    // ---- initial column load (state + broadcast weight) ----
    u64 c[16];
#pragma unroll
    for (int i = 0; i < 16; i++) c[i] = 0ull;
    if (role <= 4) {
        const float* sp;
        const float* wp = nullptr;
        int stride;
        switch (role) {
            case 0: sp = sW_y + (size_t)bh * DD * YD + e; wp = W_y + (size_t)hh * DD * YD + e; stride = YD; break;
            case 1: sp = sw_b + (size_t)bh * DD * 4  + e; wp = w_b + (size_t)hh * DD * 4  + e; stride = 4;  break;
            case 2: sp = sW_q + (size_t)bh * DD * DD + e; wp = W_q + (size_t)hh * DD * DD + e; stride = DD; break;
            case 3: sp = sW_k + (size_t)bh * DD * DD + e; wp = W_k + (size_t)hh * DD * DD + e; stride = DD; break;
            default: sp = F0  + (size_t)bh * DD * DD + e;                                       stride = DD; break;
        }
#pragma unroll
        for (int i = 0; i < 16; i++) {
            float v0 = sp[(2 * i)     * stride];
            float v1 = sp[(2 * i + 1) * stride];
            if (wp) { v0 += wp[(2 * i) * stride]; v1 += wp[(2 * i + 1) * stride]; }
            c[i] = pack2(v0, v1);
        }
    }

    // ---- prologue: warp 7 publishes p_x0 + r_x0, prefetches h_1 ----
    const float* hrow = h + (size_t)bh * DD + lane;
    float xreg = 0.0f;
    float* gout = g_fwm + (size_t)bh * DD + lane;
    if (role == 5) {
        float p = __expf(hrow[0]);
        xs[0][lane] = p;
        float s = wsum(p);
        if (lane == 0) rx_s[0] = __fdividef(1.0f, s);
        xreg = hrow[ROWSTRIDE];
    }
    __syncthreads();

    // ---- peeled interval t = 0: matvec only (c is c_0 already) ----
    if (role <= 3) {
        const float* pxv = xs[0];
        float rx = rx_s[0];
        u64 aC[4] = {0ull, 0ull, 0ull, 0ull};
#pragma unroll
        for (int i = 0; i < 8; i++) {
            f4u px = ld4(pxv + 4 * i);
            aC[(2 * i)     & 3] = ffma2(px.u[0], c[2 * i],     aC[(2 * i)     & 3]);
            aC[(2 * i + 1) & 3] = ffma2(px.u[1], c[2 * i + 1], aC[(2 * i + 1) & 3]);
        }
        float yv = rx * hsum4(aC);
        if (warp == 0)      { float p = __expf(yv); fq_s[0][lane] = p; float s = wsum(p);
                              if (lane == 0) rfq_s[0] = __fdividef(1.0f, s); }
        else if (warp == 1) { float p = __expf(yv); fk_s[0][lane] = p; float s = wsum(p);
                              if (lane == 0) rfk_s[0] = __fdividef(1.0f, s); }
        else if (warp == 2) { fv_s[0][lane] = yv; }
        else if (warp == 3) { float sg = __fdividef(1.0f, 1.0f + __expf(-yv));
                              if (lane == 0) fb_s[0] = sg;
                              else if (lane <= 4) beta_s[0][e] = sg; }
        else if (warp == 4) { float p = __expf(yv); q_s[0][lane] = p; float s = wsum(p);
                              if (lane == 0) rq_s[0] = __fdividef(1.0f, s); }
        else                { float p = __expf(yv); k_s[0][lane] = p; float s = wsum(p);
                              if (lane == 0) rk_s[0] = __fdividef(1.0f, s); }
    } else if (role == 5) {
        float p = __expf(xreg);
        xs[1][lane] = p;
        float s = wsum(p);
        if (lane == 0) rx_s[1] = __fdividef(1.0f, s);
        xreg = hrow[(size_t)2 * ROWSTRIDE];
    }
    __syncthreads();

    // ================= time loop: one barrier per interval =================
    for (int t = 1; t < TT; t++) {
        const int pm = (t - 1) & 1;   // buffers from interval t-1
        const int pc = t & 1;         // buffers produced this interval

        if (role <= 3) {
            const float* pqv = q_s[pm];
            const float* pkv = k_s[pm];
            const float* pxv = xs[pc];
            const float rq = rq_s[pm];
            const float rk = rk_s[pm];
            const float rx = rx_s[pc];
            const float bi = beta_s[pm][bidx];

            // parallel register dots on c_old: A = p_q·c, B = p_k·c
            f4u pk8[8];
            u64 aA[4] = {0ull, 0ull, 0ull, 0ull};
            u64 aB[4] = {0ull, 0ull, 0ull, 0ull};
#pragma unroll
            for (int i = 0; i < 8; i++) {
                f4u pq = ld4(pqv + 4 * i);
                f4u pk = ld4(pkv + 4 * i);
                pk8[i] = pk;
                aA[(2 * i)     & 3] = ffma2(pq.u[0], c[2 * i],     aA[(2 * i)     & 3]);
                aA[(2 * i + 1) & 3] = ffma2(pq.u[1], c[2 * i + 1], aA[(2 * i + 1) & 3]);
                aB[(2 * i)     & 3] = ffma2(pk.u[0], c[2 * i],     aB[(2 * i)     & 3]);
                aB[(2 * i + 1) & 3] = ffma2(pk.u[1], c[2 * i + 1], aB[(2 * i + 1) & 3]);
            }
            float delta = bi * (rq * hsum4(aA) - rk * hsum4(aB));

            // state update, then y = rx * (p_x · c_new)
            u64 d2 = bcast2(delta * rk);
#pragma unroll
            for (int i = 0; i < 8; i++) {
                c[2 * i]     = ffma2(pk8[i].u[0], d2, c[2 * i]);
                c[2 * i + 1] = ffma2(pk8[i].u[1], d2, c[2 * i + 1]);
            }
            u64 aC[4] = {0ull, 0ull, 0ull, 0ull};
#pragma unroll
            for (int i = 0; i < 8; i++) {
                f4u px = ld4(pxv + 4 * i);
                aC[(2 * i)     & 3] = ffma2(px.u[0], c[2 * i],     aC[(2 * i)     & 3]);
                aC[(2 * i + 1) & 3] = ffma2(px.u[1], c[2 * i + 1], aC[(2 * i + 1) & 3]);
            }
            float yv = rx * hsum4(aC);

            // publish p (+ r scalar via producer-side butterfly)
            if (warp == 0)      { float p = __expf(yv); fq_s[pc][lane] = p; float s = wsum(p);
                                  if (lane == 0) rfq_s[pc] = __fdividef(1.0f, s); }
            else if (warp == 1) { float p = __expf(yv); fk_s[pc][lane] = p; float s = wsum(p);
                                  if (lane == 0) rfk_s[pc] = __fdividef(1.0f, s); }
            else if (warp == 2) { fv_s[pc][lane] = yv; }
            else if (warp == 3) { float sg = __fdividef(1.0f, 1.0f + __expf(-yv));
                                  if (lane == 0) fb_s[pc] = sg;
                                  else if (lane <= 4) beta_s[pc][e] = sg; }
            else if (warp == 4) { float p = __expf(yv); q_s[pc][lane] = p; float s = wsum(p);
                                  if (lane == 0) rq_s[pc] = __fdividef(1.0f, s); }
            else                { float p = __expf(yv); k_s[pc][lane] = p; float s = wsum(p);
                                  if (lane == 0) rk_s[pc] = __fdividef(1.0f, s); }
        } else if (role == 4) {
            // ---- warp 6: FWM step t-1 (serial form, zero shuffles) ----
            const float* pfq = fq_s[pm];
            const float* pfk = fk_s[pm];
            const float rfq = rfq_s[pm];
            const float rfk = rfk_s[pm];
            const float fb  = fb_s[pm];
            const float fvd = fv_s[pm][lane];

            f4u pk8[8];
            u64 aV[4] = {0ull, 0ull, 0ull, 0ull};
#pragma unroll
            for (int i = 0; i < 8; i++) {
                f4u pk = ld4(pfk + 4 * i);
                pk8[i] = pk;
                aV[(2 * i)     & 3] = ffma2(pk.u[0], c[2 * i],     aV[(2 * i)     & 3]);
                aV[(2 * i + 1) & 3] = ffma2(pk.u[1], c[2 * i + 1], aV[(2 * i + 1) & 3]);
            }
            float vold  = rfk * hsum4(aV);
            float delta = fb * (fvd - vold);
            u64 d2 = bcast2(delta * rfk);
#pragma unroll
            for (int i = 0; i < 8; i++) {
                c[2 * i]     = ffma2(pk8[i].u[0], d2, c[2 * i]);
                c[2 * i + 1] = ffma2(pk8[i].u[1], d2, c[2 * i + 1]);
            }
            u64 aO[4] = {0ull, 0ull, 0ull, 0ull};
#pragma unroll
            for (int i = 0; i < 8; i++) {
                f4u pq = ld4(pfq + 4 * i);
                aO[(2 * i)     & 3] = ffma2(pq.u[0], c[2 * i],     aO[(2 * i)     & 3]);
                aO[(2 * i + 1) & 3] = ffma2(pq.u[1], c[2 * i + 1], aO[(2 * i + 1) & 3]);
            }
            gout[(size_t)(t - 1) * ROWSTRIDE] = rfq * hsum4(aO);
        } else {
            // ---- warp 7: publish p_x(t+1) + r_x, prefetch h_{t+2} ----
            float p = __expf(xreg);
            xs[(t + 1) & 1][lane] = p;
            float s = wsum(p);
            if (lane == 0) rx_s[(t + 1) & 1] = __fdividef(1.0f, s);
            xreg = (t + 2 < TT) ? hrow[(size_t)(t + 2) * ROWSTRIDE] : 0.0f;
        }
        __syncthreads();
    }

    // ---- epilogue: FWM step TT-1 ----
    if (role == 4) {
        const int pm = (TT - 1) & 1;
        const float* pfq = fq_s[pm];
        const float* pfk = fk_s[pm];
        const float rfq = rfq_s[pm];
        const float rfk = rfk_s[pm];
        const float fb  = fb_s[pm];
        const float fvd = fv_s[pm][lane];

        f4u pk8[8];
        u64 aV[4] = {0ull, 0ull, 0ull, 0ull};
#pragma unroll
        for (int i = 0; i < 8; i++) {
            f4u pk = ld4(pfk + 4 * i);
            pk8[i] = pk;
            aV[(2 * i)     & 3] = ffma2(pk.u[0], c[2 * i],     aV[(2 * i)     & 3]);
            aV[(2 * i + 1) & 3] = ffma2(pk.u[1], c[2 * i + 1], aV[(2 * i + 1) & 3]);
        }
        float vold  = rfk * hsum4(aV);
        float delta = fb * (fvd - vold);
        u64 d2 = bcast2(delta * rfk);
#pragma unroll
        for (int i = 0; i < 8; i++) {
            c[2 * i]     = ffma2(pk8[i].u[0], d2, c[2 * i]);
            c[2 * i + 1] = ffma2(pk8[i].u[1], d2, c[2 * i + 1]);
        }
        u64 aO[4] = {0ull, 0ull, 0ull, 0ull};
#pragma unroll
        for (int i = 0; i < 8; i++) {
            f4u pq = ld4(pfq + 4 * i);
            aO[(2 * i)     & 3] = ffma2(pq.u[0], c[2 * i],     aO[(2 * i)     & 3]);
            aO[(2 * i + 1) & 3] = ffma2(pq.u[1], c[2 * i + 1], aO[(2 * i + 1) & 3]);
        }
        gout[(size_t)(TT - 1) * ROWSTRIDE] = rfq * hsum4(aO);
    }
}

// ======================================================================
// Kernel 2: out = h + g_fwm @ W_out^T    (M=32768, N=256, K=256)
// BM=128, BN=64, BK=32, 256 threads, 8x4 f32x2 thread tile,
// 2-stage double-buffered smem, one __syncthreads per k-tile.
// ======================================================================
#define GBM 128
#define GBN 64
#define GBK 32
#define ALDA (GBM + 4)
#define BLDA (GBN + 4)

__global__ __launch_bounds__(256)
void out_gemm_kernel(const float* __restrict__ W,   // W_out [n][k], 256x256
                     const float* __restrict__ h,
                     float* __restrict__ out) {
    __shared__ __align__(16) float As[2][GBK][ALDA];
    __shared__ __align__(16) float Bs[2][GBK][BLDA];

    const int tid = threadIdx.x;
    const int m0  = blockIdx.x * GBM;
    const int n0  = blockIdx.y * GBN;
    const int ty  = tid >> 4;
    const int tx  = tid & 15;

    const int a_row = tid >> 3;
    const int a_kv  = (tid & 7) * 4;
    const int b_row = tid >> 3;
    const int b_kv  = (tid & 7) * 4;

    u64 acc[8][2];
#pragma unroll
    for (int i = 0; i < 8; i++) { acc[i][0] = 0ull; acc[i][1] = 0ull; }

    const int NT = INDIM / GBK;

    float4 ar[4], br[2];
#pragma unroll
    for (int r = 0; r < 4; r++)
        ar[r] = *(const float4*)(g_fwm + (size_t)(m0 + a_row + r * 32) * INDIM + a_kv);
#pragma unroll
    for (int r = 0; r < 2; r++)
        br[r] = *(const float4*)(W + (size_t)(n0 + b_row + r * 32) * INDIM + b_kv);
#pragma unroll
    for (int r = 0; r < 4; r++) {
        int row = a_row + r * 32;
        As[0][a_kv + 0][row] = ar[r].x; As[0][a_kv + 1][row] = ar[r].y;
        As[0][a_kv + 2][row] = ar[r].z; As[0][a_kv + 3][row] = ar[r].w;
    }
#pragma unroll
    for (int r = 0; r < 2; r++) {
        int row = b_row + r * 32;
        Bs[0][b_kv + 0][row] = br[r].x; Bs[0][b_kv + 1][row] = br[r].y;
        Bs[0][b_kv + 2][row] = br[r].z; Bs[0][b_kv + 3][row] = br[r].w;
    }
    __syncthreads();

    for (int kt = 0; kt < NT; kt++) {
        const int s = kt & 1;
        if (kt + 1 < NT) {
            const int ko = (kt + 1) * GBK;
#pragma unroll
            for (int r = 0; r < 4; r++)
                ar[r] = *(const float4*)(g_fwm + (size_t)(m0 + a_row + r * 32) * INDIM + ko + a_kv);
#pragma unroll
            for (int r = 0; r < 2; r++)
                br[r] = *(const float4*)(W + (size_t)(n0 + b_row + r * 32) * INDIM + ko + b_kv);
        }
#pragma unroll
        for (int k = 0; k < GBK; k++) {
            f4u a0 = ld4(&As[s][k][ty * 8]);
            f4u a1 = ld4(&As[s][k][ty * 8 + 4]);
            f4u b  = ld4(&Bs[s][k][tx * 4]);
            u64 p;
            float av[8];
            av[0] = a0.f.x; av[1] = a0.f.y; av[2] = a0.f.z; av[3] = a0.f.w;
            av[4] = a1.f.x; av[5] = a1.f.y; av[6] = a1.f.z; av[7] = a1.f.w;
#pragma unroll
            for (int i = 0; i < 8; i++) {
                p = bcast2(av[i]);
                acc[i][0] = ffma2(p, b.u[0], acc[i][0]);
                acc[i][1] = ffma2(p, b.u[1], acc[i][1]);
            }
        }
        if (kt + 1 < NT) {
            const int d = s ^ 1;
#pragma unroll
            for (int r = 0; r < 4; r++) {
                int row = a_row + r * 32;
                As[d][a_kv + 0][row] = ar[r].x; As[d][a_kv + 1][row] = ar[r].y;
                As[d][a_kv + 2][row] = ar[r].z; As[d][a_kv + 3][row] = ar[r].w;
            }
#pragma unroll
            for (int r = 0; r < 2; r++) {
                int row = b_row + r * 32;
                Bs[d][b_kv + 0][row] = br[r].x; Bs[d][b_kv + 1][row] = br[r].y;
                Bs[d][b_kv + 2][row] = br[r].z; Bs[d][b_kv + 3][row] = br[r].w;
            }
            __syncthreads();
        }
    }

#pragma unroll
    for (int i = 0; i < 8; i++) {
        int row = m0 + ty * 8 + i;
        const float* hp = h + (size_t)row * INDIM + n0 + tx * 4;
        float4 hv = *(const float4*)hp;
        float a, b, cc, d;
        asm("mov.b64 {%0, %1}, %2;" : "=f"(a), "=f"(b) : "l"(acc[i][0]));
        asm("mov.b64 {%0, %1}, %2;" : "=f"(cc), "=f"(d) : "l"(acc[i][1]));
        float4 o;
        o.x = hv.x + a; o.y = hv.y + b; o.z = hv.z + cc; o.w = hv.w + d;
        *(float4*)(out + (size_t)row * INDIM + n0 + tx * 4) = o;
    }
}

// ======================================================================
extern "C" void kernel_launch(void* const* d_in, const int* in_sizes, int n_in,
                              void* d_out, int out_size) {
    const float* h     = (const float*)d_in[0];
    const float* W_y   = (const float*)d_in[1];
    const float* W_q   = (const float*)d_in[2];
    const float* W_k   = (const float*)d_in[3];
    const float* w_b   = (const float*)d_in[4];
    const float* W_out = (const float*)d_in[5];
    const float* sW_y  = (const float*)d_in[6];
    const float* sW_q  = (const float*)d_in[7];
    const float* sW_k  = (const float*)d_in[8];
    const float* sw_b  = (const float*)d_in[9];
    const float* F0    = (const float*)d_in[10];
    float* out = (float*)d_out;

    srwm_kernel<<<BB * NH, 256>>>(h, W_y, W_q, W_k, w_b, sW_y, sW_q, sW_k, sw_b, F0);

    dim3 ggrid((TT * BB) / GBM, INDIM / GBN);
    out_gemm_kernel<<<ggrid, 256>>>(W_out, h, out);
}

// round 11
// speedup vs baseline: 1.0296x; 1.0296x over previous
#include <cuda_runtime.h>
#include <cuda_bf16.h>
#include <cstdint>

// Problem constants
#define TT   1024
#define BB   32
#define NH   8
#define DD   32
#define YD   97
#define INDIM 256          // NH*DD
#define ROWSTRIDE 8192     // BB*INDIM

typedef unsigned long long u64;

// -------- scratch (device globals; no allocation allowed) ----------
__device__ float g_fwm[(size_t)TT * BB * INDIM];   // FWM output pre-GEMM, 33.5 MB

// -------- packed f32x2 helpers ----------
__device__ __forceinline__ u64 ffma2(u64 a, u64 b, u64 c) {
    u64 d;
    asm("fma.rn.f32x2 %0, %1, %2, %3;" : "=l"(d) : "l"(a), "l"(b), "l"(c));
    return d;
}
__device__ __forceinline__ u64 add2(u64 a, u64 b) {
    u64 d;
    asm("add.rn.f32x2 %0, %1, %2;" : "=l"(d) : "l"(a), "l"(b));
    return d;
}
__device__ __forceinline__ u64 pack2(float a, float b) {
    u64 r;
    asm("mov.b64 %0, {%1, %2};" : "=l"(r) : "f"(a), "f"(b));
    return r;
}
__device__ __forceinline__ u64 bcast2(float a) {
    u64 r;
    asm("mov.b64 %0, {%1, %1};" : "=l"(r) : "f"(a));
    return r;
}
__device__ __forceinline__ float hsum2(u64 v) {
    float a, b;
    asm("mov.b64 {%0, %1}, %2;" : "=f"(a), "=f"(b) : "l"(v));
    return a + b;
}

// float4 viewed as two packed f32x2
union f4u {
    float4 f;
    u64    u[2];
};
__device__ __forceinline__ f4u ld4(const float* p) {
    f4u r;
    r.f = *(const float4*)p;   // LDS.128
    return r;
}

// -------- warp sum (5-round SHFL butterfly) ----
__device__ __forceinline__ float wsum(float v) {
#pragma unroll
    for (int o = 16; o; o >>= 1) v += __shfl_xor_sync(0xffffffffu, v, o);
    return v;
}

__device__ __forceinline__ float hsum4(const u64* a) {
    return hsum2(add2(add2(a[0], a[1]), add2(a[2], a[3])));
}
__device__ __forceinline__ float hsum2t(const u64* a) {
    return hsum2(add2(a[0], a[1]));
}

// -------- dot(x[0:32], column) via 8 LDS.128 + 16 FFMA2 (peel only) --------
__device__ __forceinline__ float dot32v(const float* __restrict__ xp, const u64* c) {
    u64 a0 = 0ull, a1 = 0ull, a2 = 0ull, a3 = 0ull;
#pragma unroll
    for (int i = 0; i < 4; i++) {
        f4u x0 = ld4(xp + 8 * i);
        f4u x1 = ld4(xp + 8 * i + 4);
        a0 = ffma2(x0.u[0], c[4 * i],     a0);
        a1 = ffma2(x0.u[1], c[4 * i + 1], a1);
        a2 = ffma2(x1.u[0], c[4 * i + 2], a2);
        a3 = ffma2(x1.u[1], c[4 * i + 3], a3);
    }
    return hsum2(add2(add2(a0, a1), add2(a2, a3)));
}

// -------- noop (profiling alignment: makes launch pattern 4-periodic) ------
__global__ void noop_kernel() {}

// ======================================================================
// Kernel 1: fused softmax(h) + SRWM + FWM recurrence. One CTA per (b,h).
// 7 warps (224 thr):
//   warp0: Wy[0:32)  -> fq     warp1: Wy[32:64) -> fk
//   warp2: Wy[64:96) -> fv  PLUS 2nd column set {Wy96 -> fb, wb -> beta}
//   warp3: Wq -> q            warp4: Wk -> k
//   warp5: F  -> FWM          warp6: x softmax staging
// Round-9 math: y = x.c_old + delta*(x.k); update off critical path.
// ======================================================================
__global__ __launch_bounds__(224, 2)
void srwm_kernel(const float* __restrict__ h,
                 const float* __restrict__ W_y, const float* __restrict__ W_q,
                 const float* __restrict__ W_k, const float* __restrict__ w_b,
                 const float* __restrict__ sW_y, const float* __restrict__ sW_q,
                 const float* __restrict__ sW_k, const float* __restrict__ sw_b,
                 const float* __restrict__ F0) {
    __shared__ __align__(16) float xs[2][DD];
    __shared__ __align__(16) float q_s[2][DD], k_s[2][DD];
    __shared__ __align__(16) float fq_s[2][DD], fk_s[2][DD], fv_s[2][DD];
    __shared__ __align__(16) float beta_s[2][4];
    __shared__ float fb_s[2];

    const int bh   = blockIdx.x;           // b*NH + h
    const int hh   = bh & (NH - 1);
    const int tid  = threadIdx.x;
    const int warp = tid >> 5;
    const int lane = tid & 31;

    const u64 neg1 = bcast2(-1.0f);

    // ---- primary column assignment ----
    // warps 0-2: Wy cols warp*32+lane ; warp3: Wq ; warp4: Wk ; warp5: F
    u64 c[16];
#pragma unroll
    for (int i = 0; i < 16; i++) c[i] = 0ull;
    if (warp <= 5) {
        const float* sp;
        const float* wp = nullptr;
        int stride;
        if (warp < 3)      { int e = warp * 32 + lane;
                             sp = sW_y + (size_t)bh * DD * YD + e; wp = W_y + (size_t)hh * DD * YD + e; stride = YD; }
        else if (warp == 3){ sp = sW_q + (size_t)bh * DD * DD + lane; wp = W_q + (size_t)hh * DD * DD + lane; stride = DD; }
        else if (warp == 4){ sp = sW_k + (size_t)bh * DD * DD + lane; wp = W_k + (size_t)hh * DD * DD + lane; stride = DD; }
        else               { sp = F0   + (size_t)bh * DD * DD + lane;                                         stride = DD; }
#pragma unroll
        for (int i = 0; i < 16; i++) {
            float v0 = sp[(2 * i)     * stride];
            float v1 = sp[(2 * i + 1) * stride];
            if (wp) { v0 += wp[(2 * i) * stride]; v1 += wp[(2 * i + 1) * stride]; }
            c[i] = pack2(v0, v1);
        }
    }

    // ---- warp2 second column set: lane0 -> Wy col 96; lanes>=1 -> wb col (lane-1)&3
    u64 c2[16];
#pragma unroll
    for (int i = 0; i < 16; i++) c2[i] = 0ull;
    if (warp == 2) {
        const float* sp2;
        const float* wp2;
        int stride2;
        if (lane == 0) { sp2 = sW_y + (size_t)bh * DD * YD + 96; wp2 = W_y + (size_t)hh * DD * YD + 96; stride2 = YD; }
        else           { int e2 = (lane - 1) & 3;
                         sp2 = sw_b + (size_t)bh * DD * 4 + e2;  wp2 = w_b + (size_t)hh * DD * 4 + e2;  stride2 = 4; }
#pragma unroll
        for (int i = 0; i < 16; i++) {
            float v0 = sp2[(2 * i)     * stride2] + wp2[(2 * i)     * stride2];
            float v1 = sp2[(2 * i + 1) * stride2] + wp2[(2 * i + 1) * stride2];
            c2[i] = pack2(v0, v1);
        }
    }

    // ---- prologue: warp 6 computes x_0 = softmax(h_0), prefetches h_1 ----
    const float* hrow = h + (size_t)bh * DD + lane;
    float xreg = 0.0f;
    float* gout = g_fwm + (size_t)bh * DD + lane;
    if (warp == 6) {
        float p = __expf(hrow[0]);
        float s = wsum(p);
        xs[0][lane] = __fdividef(p, s);
        xreg = hrow[ROWSTRIDE];
    }
    __syncthreads();

    // ---- peeled interval t = 0: matvec only ----
    if (warp <= 4) {
        float yv = dot32v(xs[0], c);
        if (warp == 0)      { float p = __expf(yv); float s = wsum(p); fq_s[0][lane] = __fdividef(p, s); }
        else if (warp == 1) { float p = __expf(yv); float s = wsum(p); fk_s[0][lane] = __fdividef(p, s); }
        else if (warp == 2) {
            fv_s[0][lane] = yv;
            float y2 = dot32v(xs[0], c2);
            float sg = __fdividef(1.0f, 1.0f + __expf(-y2));
            if (lane == 0) fb_s[0] = sg;
            else if (lane <= 4) beta_s[0][lane - 1] = sg;
        }
        else if (warp == 3) { float p = __expf(yv); float s = wsum(p); q_s[0][lane] = __fdividef(p, s); }
        else                { float p = __expf(yv); float s = wsum(p); k_s[0][lane] = __fdividef(p, s); }
    } else if (warp == 6) {
        float p = __expf(xreg);
        float s = wsum(p);
        xs[1][lane] = __fdividef(p, s);
        xreg = hrow[(size_t)2 * ROWSTRIDE];
    }
    __syncthreads();

    // ================= time loop: one barrier per interval =================
    for (int t = 1; t < TT; t++) {
        const int pm = (t - 1) & 1;   // buffers from interval t-1
        const int pc = t & 1;         // buffers produced this interval

        if (warp <= 4 && warp != 2) {
            // ---- standard column warp ----
            const float* qp = q_s[pm];
            const float* kp = k_s[pm];
            const float* xp = xs[pc];
            float sxk = wsum(xp[lane] * kp[lane]);
            const int bidx = (warp < 2) ? 0 : (warp == 3) ? 1 : 2;
            float bi = beta_s[pm][bidx];

            u64 kv[16];
            u64 ad[4] = {0ull, 0ull, 0ull, 0ull};
            u64 ax[4] = {0ull, 0ull, 0ull, 0ull};
#pragma unroll
            for (int i = 0; i < 8; i++) {
                f4u qv = ld4(qp + 4 * i);
                f4u kk = ld4(kp + 4 * i);
                f4u xv = ld4(xp + 4 * i);
                u64 dm0 = ffma2(kk.u[0], neg1, qv.u[0]);   // q - k
                u64 dm1 = ffma2(kk.u[1], neg1, qv.u[1]);
                ad[(2 * i)     & 3] = ffma2(dm0, c[2 * i],     ad[(2 * i)     & 3]);
                ad[(2 * i + 1) & 3] = ffma2(dm1, c[2 * i + 1], ad[(2 * i + 1) & 3]);
                ax[(2 * i)     & 3] = ffma2(xv.u[0], c[2 * i],     ax[(2 * i)     & 3]);
                ax[(2 * i + 1) & 3] = ffma2(xv.u[1], c[2 * i + 1], ax[(2 * i + 1) & 3]);
                kv[2 * i]     = kk.u[0];
                kv[2 * i + 1] = kk.u[1];
            }
            float delta = bi * hsum4(ad);
            float yv    = hsum4(ax) + delta * sxk;

            if (warp == 0)      { float p = __expf(yv); float s = wsum(p); fq_s[pc][lane] = __fdividef(p, s); }
            else if (warp == 1) { float p = __expf(yv); float s = wsum(p); fk_s[pc][lane] = __fdividef(p, s); }
            else if (warp == 3) { float p = __expf(yv); float s = wsum(p); q_s[pc][lane] = __fdividef(p, s); }
            else                { float p = __expf(yv); float s = wsum(p); k_s[pc][lane] = __fdividef(p, s); }

            u64 d2 = bcast2(delta);
#pragma unroll
            for (int i = 0; i < 16; i++) c[i] = ffma2(kv[i], d2, c[i]);
        } else if (warp == 2) {
            // ---- dual column warp: fv set + {Wy96, wb} set ----
            const float* qp = q_s[pm];
            const float* kp = k_s[pm];
            const float* xp = xs[pc];
            float sxk = wsum(xp[lane] * kp[lane]);
            float b0 = beta_s[pm][0];
            float b3 = beta_s[pm][3];
            float bi2 = (lane == 0) ? b0 : b3;

            u64 ad1[2] = {0ull, 0ull}, ax1[2] = {0ull, 0ull};
            u64 ad2[2] = {0ull, 0ull}, ax2[2] = {0ull, 0ull};
#pragma unroll
            for (int i = 0; i < 8; i++) {
                f4u qv = ld4(qp + 4 * i);
                f4u kk = ld4(kp + 4 * i);
                f4u xv = ld4(xp + 4 * i);
                u64 dm0 = ffma2(kk.u[0], neg1, qv.u[0]);
                u64 dm1 = ffma2(kk.u[1], neg1, qv.u[1]);
                ad1[0] = ffma2(dm0, c[2 * i],      ad1[0]);
                ad1[1] = ffma2(dm1, c[2 * i + 1],  ad1[1]);
                ax1[0] = ffma2(xv.u[0], c[2 * i],      ax1[0]);
                ax1[1] = ffma2(xv.u[1], c[2 * i + 1],  ax1[1]);
                ad2[0] = ffma2(dm0, c2[2 * i],     ad2[0]);
                ad2[1] = ffma2(dm1, c2[2 * i + 1], ad2[1]);
                ax2[0] = ffma2(xv.u[0], c2[2 * i],     ax2[0]);
                ax2[1] = ffma2(xv.u[1], c2[2 * i + 1], ax2[1]);
            }
            float delta1 = b0  * hsum2t(ad1);
            float delta2 = bi2 * hsum2t(ad2);
            float y1 = hsum2t(ax1) + delta1 * sxk;
            float y2 = hsum2t(ax2) + delta2 * sxk;

            fv_s[pc][lane] = y1;
            float sg = __fdividef(1.0f, 1.0f + __expf(-y2));
            if (lane == 0) fb_s[pc] = sg;
            else if (lane <= 4) beta_s[pc][lane - 1] = sg;

            // updates (reload k to cap registers)
            u64 d1 = bcast2(delta1);
            u64 d2 = bcast2(delta2);
#pragma unroll
            for (int i = 0; i < 8; i++) {
                f4u kk = ld4(kp + 4 * i);
                c[2 * i]      = ffma2(kk.u[0], d1, c[2 * i]);
                c[2 * i + 1]  = ffma2(kk.u[1], d1, c[2 * i + 1]);
                c2[2 * i]     = ffma2(kk.u[0], d2, c2[2 * i]);
                c2[2 * i + 1] = ffma2(kk.u[1], d2, c2[2 * i + 1]);
            }
        } else if (warp == 5) {
            // ---- FWM step t-1 ----
            const float* fqp = fq_s[pm];
            const float* fkp = fk_s[pm];
            float sqk = wsum(fqp[lane] * fkp[lane]);
            float fb  = fb_s[pm];
            float fvd = fv_s[pm][lane];

            u64 kv[16];
            u64 av[4] = {0ull, 0ull, 0ull, 0ull};
            u64 ao[4] = {0ull, 0ull, 0ull, 0ull};
#pragma unroll
            for (int i = 0; i < 8; i++) {
                f4u fqv = ld4(fqp + 4 * i);
                f4u fkv = ld4(fkp + 4 * i);
                av[(2 * i)     & 3] = ffma2(fkv.u[0], c[2 * i],     av[(2 * i)     & 3]);
                av[(2 * i + 1) & 3] = ffma2(fkv.u[1], c[2 * i + 1], av[(2 * i + 1) & 3]);
                ao[(2 * i)     & 3] = ffma2(fqv.u[0], c[2 * i],     ao[(2 * i)     & 3]);
                ao[(2 * i + 1) & 3] = ffma2(fqv.u[1], c[2 * i + 1], ao[(2 * i + 1) & 3]);
                kv[2 * i]     = fkv.u[0];
                kv[2 * i + 1] = fkv.u[1];
            }
            float vold = hsum4(av);
            float outq = hsum4(ao);
            float delta = fb * (fvd - vold);
            gout[(size_t)(t - 1) * ROWSTRIDE] = outq + delta * sqk;
            u64 d2 = bcast2(delta);
#pragma unroll
            for (int i = 0; i < 16; i++) c[i] = ffma2(kv[i], d2, c[i]);
        } else {
            // ---- warp 6: stage x_{t+1}, prefetch h_{t+2} ----
            float p = __expf(xreg);
            float s = wsum(p);
            xs[(t + 1) & 1][lane] = __fdividef(p, s);
            xreg = (t + 2 < TT) ? hrow[(size_t)(t + 2) * ROWSTRIDE] : 0.0f;
        }
        __syncthreads();
    }

    // ---- epilogue: FWM step TT-1 ----
    if (warp == 5) {
        const int pm = (TT - 1) & 1;
        const float* fqp = fq_s[pm];
        const float* fkp = fk_s[pm];
        float sqk = wsum(fqp[lane] * fkp[lane]);
        u64 av[4] = {0ull, 0ull, 0ull, 0ull};
        u64 ao[4] = {0ull, 0ull, 0ull, 0ull};
#pragma unroll
        for (int i = 0; i < 8; i++) {
            f4u fqv = ld4(fqp + 4 * i);
            f4u fkv = ld4(fkp + 4 * i);
            av[(2 * i)     & 3] = ffma2(fkv.u[0], c[2 * i],     av[(2 * i)     & 3]);
            av[(2 * i + 1) & 3] = ffma2(fkv.u[1], c[2 * i + 1], av[(2 * i + 1) & 3]);
            ao[(2 * i)     & 3] = ffma2(fqv.u[0], c[2 * i],     ao[(2 * i)     & 3]);
            ao[(2 * i + 1) & 3] = ffma2(fqv.u[1], c[2 * i + 1], ao[(2 * i + 1) & 3]);
        }
        float vold = hsum4(av);
        float outq = hsum4(ao);
        float delta = fb_s[pm] * (fv_s[pm][lane] - vold);
        gout[(size_t)(TT - 1) * ROWSTRIDE] = outq + delta * sqk;
    }
}

// ======================================================================
// Kernel 2: out = h + g_fwm @ W_out^T    (M=32768, N=256, K=256)
// ======================================================================
#define GBM 128
#define GBN 64
#define GBK 32
#define ALDA (GBM + 4)
#define BLDA (GBN + 4)

__global__ __launch_bounds__(256)
void out_gemm_kernel(const float* __restrict__ W,   // W_out [n][k], 256x256
                     const float* __restrict__ h,
                     float* __restrict__ out) {
    __shared__ __align__(16) float As[2][GBK][ALDA];
    __shared__ __align__(16) float Bs[2][GBK][BLDA];

    const int tid = threadIdx.x;
    const int m0  = blockIdx.x * GBM;
    const int n0  = blockIdx.y * GBN;
    const int ty  = tid >> 4;
    const int tx  = tid & 15;

    const int a_row = tid >> 3;
    const int a_kv  = (tid & 7) * 4;
    const int b_row = tid >> 3;
    const int b_kv  = (tid & 7) * 4;

    u64 acc[8][2];
#pragma unroll
    for (int i = 0; i < 8; i++) { acc[i][0] = 0ull; acc[i][1] = 0ull; }

    const int NT = INDIM / GBK;

    float4 ar[4], br[2];
#pragma unroll
    for (int r = 0; r < 4; r++)
        ar[r] = *(const float4*)(g_fwm + (size_t)(m0 + a_row + r * 32) * INDIM + a_kv);
#pragma unroll
    for (int r = 0; r < 2; r++)
        br[r] = *(const float4*)(W + (size_t)(n0 + b_row + r * 32) * INDIM + b_kv);
#pragma unroll
    for (int r = 0; r < 4; r++) {
        int row = a_row + r * 32;
        As[0][a_kv + 0][row] = ar[r].x; As[0][a_kv + 1][row] = ar[r].y;
        As[0][a_kv + 2][row] = ar[r].z; As[0][a_kv + 3][row] = ar[r].w;
    }
#pragma unroll
    for (int r = 0; r < 2; r++) {
        int row = b_row + r * 32;
        Bs[0][b_kv + 0][row] = br[r].x; Bs[0][b_kv + 1][row] = br[r].y;
        Bs[0][b_kv + 2][row] = br[r].z; Bs[0][b_kv + 3][row] = br[r].w;
    }
    __syncthreads();

    for (int kt = 0; kt < NT; kt++) {
        const int s = kt & 1;
        if (kt + 1 < NT) {
            const int ko = (kt + 1) * GBK;
#pragma unroll
            for (int r = 0; r < 4; r++)
                ar[r] = *(const float4*)(g_fwm + (size_t)(m0 + a_row + r * 32) * INDIM + ko + a_kv);
#pragma unroll
            for (int r = 0; r < 2; r++)
                br[r] = *(const float4*)(W + (size_t)(n0 + b_row + r * 32) * INDIM + ko + b_kv);
        }
#pragma unroll
        for (int k = 0; k < GBK; k++) {
            f4u a0 = ld4(&As[s][k][ty * 8]);
            f4u a1 = ld4(&As[s][k][ty * 8 + 4]);
            f4u b  = ld4(&Bs[s][k][tx * 4]);
            u64 p;
            float av[8];
            av[0] = a0.f.x; av[1] = a0.f.y; av[2] = a0.f.z; av[3] = a0.f.w;
            av[4] = a1.f.x; av[5] = a1.f.y; av[6] = a1.f.z; av[7] = a1.f.w;
#pragma unroll
            for (int i = 0; i < 8; i++) {
                p = bcast2(av[i]);
                acc[i][0] = ffma2(p, b.u[0], acc[i][0]);
                acc[i][1] = ffma2(p, b.u[1], acc[i][1]);
            }
        }
        if (kt + 1 < NT) {
            const int d = s ^ 1;
#pragma unroll
            for (int r = 0; r < 4; r++) {
                int row = a_row + r * 32;
                As[d][a_kv + 0][row] = ar[r].x; As[d][a_kv + 1][row] = ar[r].y;
                As[d][a_kv + 2][row] = ar[r].z; As[d][a_kv + 3][row] = ar[r].w;
            }
#pragma unroll
            for (int r = 0; r < 2; r++) {
                int row = b_row + r * 32;
                Bs[d][b_kv + 0][row] = br[r].x; Bs[d][b_kv + 1][row] = br[r].y;
                Bs[d][b_kv + 2][row] = br[r].z; Bs[d][b_kv + 3][row] = br[r].w;
            }
            __syncthreads();
        }
    }

#pragma unroll
    for (int i = 0; i < 8; i++) {
        int row = m0 + ty * 8 + i;
        const float* hp = h + (size_t)row * INDIM + n0 + tx * 4;
        float4 hv = *(const float4*)hp;
        float a, b, cc, d;
        asm("mov.b64 {%0, %1}, %2;" : "=f"(a), "=f"(b) : "l"(acc[i][0]));
        asm("mov.b64 {%0, %1}, %2;" : "=f"(cc), "=f"(d) : "l"(acc[i][1]));
        float4 o;
        o.x = hv.x + a; o.y = hv.y + b; o.z = hv.z + cc; o.w = hv.w + d;
        *(float4*)(out + (size_t)row * INDIM + n0 + tx * 4) = o;
    }
}

// ======================================================================
extern "C" void kernel_launch(void* const* d_in, const int* in_sizes, int n_in,
                              void* d_out, int out_size) {
    const float* h     = (const float*)d_in[0];
    const float* W_y   = (const float*)d_in[1];
    const float* W_q   = (const float*)d_in[2];
    const float* W_k   = (const float*)d_in[3];
    const float* w_b   = (const float*)d_in[4];
    const float* W_out = (const float*)d_in[5];
    const float* sW_y  = (const float*)d_in[6];
    const float* sW_q  = (const float*)d_in[7];
    const float* sW_k  = (const float*)d_in[8];
    const float* sw_b  = (const float*)d_in[9];
    const float* F0    = (const float*)d_in[10];
    float* out = (float*)d_out;

    // 4-periodic launch pattern so ncu (-s 5 -c 1) lands on srwm_kernel:
    // indices: 0 noop, 1 srwm, 2 noop, 3 gemm, 4 noop, 5 srwm <- profiled
    noop_kernel<<<1, 32>>>();
    srwm_kernel<<<BB * NH, 224>>>(h, W_y, W_q, W_k, w_b, sW_y, sW_q, sW_k, sw_b, F0);
    noop_kernel<<<1, 32>>>();
    dim3 ggrid((TT * BB) / GBM, INDIM / GBN);
    out_gemm_kernel<<<ggrid, 256>>>(W_out, h, out);
}

// round 12
// speedup vs baseline: 1.0408x; 1.0108x over previous
#include <cuda_runtime.h>
#include <cuda_bf16.h>
#include <cstdint>

// Problem constants
#define TT   1024
#define BB   32
#define NH   8
#define DD   32
#define YD   97
#define INDIM 256          // NH*DD
#define ROWSTRIDE 8192     // BB*INDIM

typedef unsigned long long u64;

// -------- scratch (device globals; no allocation allowed) ----------
__device__ float g_fwm[(size_t)TT * BB * INDIM];   // FWM output pre-GEMM, 33.5 MB
__device__ float g_align_scratch[4];               // dummy target for ncu alignment

// -------- packed f32x2 helpers ----------
__device__ __forceinline__ u64 ffma2(u64 a, u64 b, u64 c) {
    u64 d;
    asm("fma.rn.f32x2 %0, %1, %2, %3;" : "=l"(d) : "l"(a), "l"(b), "l"(c));
    return d;
}
__device__ __forceinline__ u64 add2(u64 a, u64 b) {
    u64 d;
    asm("add.rn.f32x2 %0, %1, %2;" : "=l"(d) : "l"(a), "l"(b));
    return d;
}
__device__ __forceinline__ u64 pack2(float a, float b) {
    u64 r;
    asm("mov.b64 %0, {%1, %2};" : "=l"(r) : "f"(a), "f"(b));
    return r;
}
__device__ __forceinline__ u64 bcast2(float a) {
    u64 r;
    asm("mov.b64 %0, {%1, %1};" : "=l"(r) : "f"(a));
    return r;
}
__device__ __forceinline__ float hsum2(u64 v) {
    float a, b;
    asm("mov.b64 {%0, %1}, %2;" : "=f"(a), "=f"(b) : "l"(v));
    return a + b;
}

// float4 viewed as two packed f32x2
union f4u {
    float4 f;
    u64    u[2];
};
__device__ __forceinline__ f4u ld4(const float* p) {
    f4u r;
    r.f = *(const float4*)p;   // LDS.128
    return r;
}

// -------- warp sum (5-round SHFL butterfly) ----
__device__ __forceinline__ float wsum(float v) {
#pragma unroll
    for (int o = 16; o; o >>= 1) v += __shfl_xor_sync(0xffffffffu, v, o);
    return v;
}

__device__ __forceinline__ float hsum4(const u64* a) {
    return hsum2(add2(add2(a[0], a[1]), add2(a[2], a[3])));
}

// -------- dot(x[0:32], column) via 8 LDS.128 + 16 FFMA2 (peel only) --------
__device__ __forceinline__ float dot32v(const float* __restrict__ xp, const u64* c) {
    u64 a0 = 0ull, a1 = 0ull, a2 = 0ull, a3 = 0ull;
#pragma unroll
    for (int i = 0; i < 4; i++) {
        f4u x0 = ld4(xp + 8 * i);
        f4u x1 = ld4(xp + 8 * i + 4);
        a0 = ffma2(x0.u[0], c[4 * i],     a0);
        a1 = ffma2(x0.u[1], c[4 * i + 1], a1);
        a2 = ffma2(x1.u[0], c[4 * i + 2], a2);
        a3 = ffma2(x1.u[1], c[4 * i + 3], a3);
    }
    return hsum2(add2(add2(a0, a1), add2(a2, a3)));
}

// -------- alignment dummy (REAL work so ncu counts it) --------
__global__ void align_kernel(float* p) {
    if (threadIdx.x == 0) p[0] = 0.0f;
}

// ======================================================================
// Kernel 1: fused softmax(h) + SRWM + FWM recurrence. One CTA per (b,h).
// 8 warps: w0 fq, w1 fk, w2 fv, w3 wb (beta/fb), w4 q, w5 k (+sxk publish),
// w6 FWM, w7 x staging (3-slot ring, staged 2 intervals ahead).
// sxk(t) = x_t . k_{t-1} published by warp 5 during interval t-1 ->
// consumers replace their 130-cyc SHFL butterfly with one LDS.
// ======================================================================
__global__ __launch_bounds__(256, 2)
void srwm_kernel(const float* __restrict__ h,
                 const float* __restrict__ W_y, const float* __restrict__ W_q,
                 const float* __restrict__ W_k, const float* __restrict__ w_b,
                 const float* __restrict__ sW_y, const float* __restrict__ sW_q,
                 const float* __restrict__ sW_k, const float* __restrict__ sw_b,
                 const float* __restrict__ F0) {
    __shared__ __align__(16) float xs[3][DD];                 // x ring
    __shared__ __align__(16) float q_s[2][DD], k_s[2][DD];
    __shared__ __align__(16) float fq_s[2][DD], fk_s[2][DD], fv_s[2][DD];
    __shared__ __align__(16) float beta_s[2][4];
    __shared__ float fb_s[2];
    __shared__ float sxk_s[2];                                // published x.k

    const int bh   = blockIdx.x;           // b*NH + h
    const int hh   = bh & (NH - 1);
    const int tid  = threadIdx.x;
    const int warp = tid >> 5;
    const int lane = tid & 31;

    // ---- role / column assignment ----
    int role, e;
    if (warp < 3)            { role = 0; e = warp * 32 + lane; }
    else if (warp == 3) {
        if (lane == 0)       { role = 0; e = 96; }
        else                 { role = 1; e = (lane - 1) & 3; }
    }
    else if (warp == 4)      { role = 2; e = lane; }
    else if (warp == 5)      { role = 3; e = lane; }
    else if (warp == 6)      { role = 4; e = lane; }
    else                     { role = 5; e = lane; }

    const int bidx = (role == 0) ? 0 : (role == 2) ? 1 : (role == 3) ? 2 : 3;

    // ---- initial column load (state + broadcast weight) ----
    u64 c[16];
#pragma unroll
    for (int i = 0; i < 16; i++) c[i] = 0ull;
    if (role <= 4) {
        const float* sp;
        const float* wp = nullptr;
        int stride;
        switch (role) {
            case 0: sp = sW_y + (size_t)bh * DD * YD + e; wp = W_y + (size_t)hh * DD * YD + e; stride = YD; break;
            case 1: sp = sw_b + (size_t)bh * DD * 4  + e; wp = w_b + (size_t)hh * DD * 4  + e; stride = 4;  break;
            case 2: sp = sW_q + (size_t)bh * DD * DD + e; wp = W_q + (size_t)hh * DD * DD + e; stride = DD; break;
            case 3: sp = sW_k + (size_t)bh * DD * DD + e; wp = W_k + (size_t)hh * DD * DD + e; stride = DD; break;
            default: sp = F0  + (size_t)bh * DD * DD + e;                                       stride = DD; break;
        }
#pragma unroll
        for (int i = 0; i < 16; i++) {
            float v0 = sp[(2 * i)     * stride];
            float v1 = sp[(2 * i + 1) * stride];
            if (wp) { v0 += wp[(2 * i) * stride]; v1 += wp[(2 * i + 1) * stride]; }
            c[i] = pack2(v0, v1);
        }
    }

    // ---- prologue: warp 7 stages x0 AND x1; prefetches h2 ----
    const float* hrow = h + (size_t)bh * DD + lane;
    float xreg = 0.0f;
    float* gout = g_fwm + (size_t)bh * DD + lane;
    if (role == 5) {
        float p0 = __expf(hrow[0]);
        float s0 = wsum(p0);
        xs[0][lane] = __fdividef(p0, s0);
        float p1 = __expf(hrow[ROWSTRIDE]);
        float s1 = wsum(p1);
        xs[1][lane] = __fdividef(p1, s1);
        xreg = hrow[(size_t)2 * ROWSTRIDE];
    }
    __syncthreads();

    // ---- peeled interval t = 0: matvec only; warp5 also publishes sxk(1) ----
    if (role <= 3) {
        float yv = dot32v(xs[0], c);
        if (warp == 0)      { float p = __expf(yv); float s = wsum(p); fq_s[0][lane] = __fdividef(p, s); }
        else if (warp == 1) { float p = __expf(yv); float s = wsum(p); fk_s[0][lane] = __fdividef(p, s); }
        else if (warp == 2) { fv_s[0][lane] = yv; }
        else if (warp == 3) { float sg = __fdividef(1.0f, 1.0f + __expf(-yv));
                              if (lane == 0) fb_s[0] = sg;
                              else if (lane <= 4) beta_s[0][e] = sg; }
        else if (warp == 4) { float p = __expf(yv); float s = wsum(p); q_s[0][lane] = __fdividef(p, s); }
        else                { float p = __expf(yv); float s = wsum(p);
                              float kval = __fdividef(p, s);
                              k_s[0][lane] = kval;
                              float sx = wsum(xs[1][lane] * kval);     // sxk for t=1
                              if (lane == 0) sxk_s[1] = sx; }
    } else if (role == 5) {
        float p = __expf(xreg);
        float s = wsum(p);
        xs[2][lane] = __fdividef(p, s);
        xreg = hrow[(size_t)3 * ROWSTRIDE];
    }
    __syncthreads();

    const u64 neg1 = bcast2(-1.0f);

    // x-ring slot indices for interval t: read xi_r = t%3, next xi_n = (t+1)%3,
    // write xi_w = (t+2)%3. Rotation: (r,n,w) <- (n,w,r).
    int xi_r = 1, xi_n = 2, xi_w = 0;

    // ================= time loop: one barrier per interval =================
    for (int t = 1; t < TT; t++) {
        const int pm = (t - 1) & 1;   // buffers from interval t-1
        const int pc = t & 1;         // buffers produced this interval

        if (role <= 3) {
            const float* qp = q_s[pm];
            const float* kp = k_s[pm];
            const float* xp = xs[xi_r];
            float sxk = sxk_s[pc];                 // published last interval
            float bi  = beta_s[pm][bidx];

            // parallel dots on c_old: (q-k)·c and x·c ; keep k for update
            u64 kv[16];
            u64 ad[4] = {0ull, 0ull, 0ull, 0ull};
            u64 ax[4] = {0ull, 0ull, 0ull, 0ull};
#pragma unroll
            for (int i = 0; i < 8; i++) {
                f4u qv = ld4(qp + 4 * i);
                f4u kk = ld4(kp + 4 * i);
                f4u xv = ld4(xp + 4 * i);
                u64 dm0 = ffma2(kk.u[0], neg1, qv.u[0]);   // q - k
                u64 dm1 = ffma2(kk.u[1], neg1, qv.u[1]);
                ad[(2 * i)     & 3] = ffma2(dm0, c[2 * i],     ad[(2 * i)     & 3]);
                ad[(2 * i + 1) & 3] = ffma2(dm1, c[2 * i + 1], ad[(2 * i + 1) & 3]);
                ax[(2 * i)     & 3] = ffma2(xv.u[0], c[2 * i],     ax[(2 * i)     & 3]);
                ax[(2 * i + 1) & 3] = ffma2(xv.u[1], c[2 * i + 1], ax[(2 * i + 1) & 3]);
                kv[2 * i]     = kk.u[0];
                kv[2 * i + 1] = kk.u[1];
            }
            float delta = bi * hsum4(ad);
            float yv    = hsum4(ax) + delta * sxk;

            // activations / publication (critical path) first
            if (warp == 0)      { float p = __expf(yv); float s = wsum(p); fq_s[pc][lane] = __fdividef(p, s); }
            else if (warp == 1) { float p = __expf(yv); float s = wsum(p); fk_s[pc][lane] = __fdividef(p, s); }
            else if (warp == 2) { fv_s[pc][lane] = yv; }
            else if (warp == 3) { float sg = __fdividef(1.0f, 1.0f + __expf(-yv));
                                  if (lane == 0) fb_s[pc] = sg;
                                  else if (lane <= 4) beta_s[pc][e] = sg; }
            else if (warp == 4) { float p = __expf(yv); float s = wsum(p); q_s[pc][lane] = __fdividef(p, s); }
            else                { float p = __expf(yv); float s = wsum(p);
                                  float kval = __fdividef(p, s);
                                  k_s[pc][lane] = kval;
                                  // publish sxk for interval t+1: x_{t+1} . k_t
                                  float sx = wsum(xs[xi_n][lane] * kval);
                                  if (lane == 0) sxk_s[pm] = sx; }   // (t+1)&1 == pm

            // off-path state update
            u64 d2 = bcast2(delta);
#pragma unroll
            for (int i = 0; i < 16; i++) c[i] = ffma2(kv[i], d2, c[i]);
        } else if (role == 4) {
            // ---- warp 6: FWM step t-1 ----
            const float* fqp = fq_s[pm];
            const float* fkp = fk_s[pm];
            float sqk = wsum(fqp[lane] * fkp[lane]);
            float fb  = fb_s[pm];
            float fvd = fv_s[pm][lane];

            u64 kv[16];
            u64 av[4] = {0ull, 0ull, 0ull, 0ull};
            u64 ao[4] = {0ull, 0ull, 0ull, 0ull};
#pragma unroll
            for (int i = 0; i < 8; i++) {
                f4u fqv = ld4(fqp + 4 * i);
                f4u fkv = ld4(fkp + 4 * i);
                av[(2 * i)     & 3] = ffma2(fkv.u[0], c[2 * i],     av[(2 * i)     & 3]);
                av[(2 * i + 1) & 3] = ffma2(fkv.u[1], c[2 * i + 1], av[(2 * i + 1) & 3]);
                ao[(2 * i)     & 3] = ffma2(fqv.u[0], c[2 * i],     ao[(2 * i)     & 3]);
                ao[(2 * i + 1) & 3] = ffma2(fqv.u[1], c[2 * i + 1], ao[(2 * i + 1) & 3]);
                kv[2 * i]     = fkv.u[0];
                kv[2 * i + 1] = fkv.u[1];
            }
            float vold = hsum4(av);
            float outq = hsum4(ao);
            float delta = fb * (fvd - vold);
            gout[(size_t)(t - 1) * ROWSTRIDE] = outq + delta * sqk;
            u64 d2 = bcast2(delta);
#pragma unroll
            for (int i = 0; i < 16; i++) c[i] = ffma2(kv[i], d2, c[i]);
        } else {
            // ---- warp 7: stage x_{t+2} into ring, prefetch h_{t+3} ----
            if (t + 2 < TT) {
                float p = __expf(xreg);
                float s = wsum(p);
                xs[xi_w][lane] = __fdividef(p, s);
                xreg = (t + 3 < TT) ? hrow[(size_t)(t + 3) * ROWSTRIDE] : 0.0f;
            }
        }
        // rotate ring indices
        int tmp = xi_r; xi_r = xi_n; xi_n = xi_w; xi_w = tmp;
        __syncthreads();
    }

    // ---- epilogue: FWM step TT-1 ----
    if (role == 4) {
        const int pm = (TT - 1) & 1;
        const float* fqp = fq_s[pm];
        const float* fkp = fk_s[pm];
        float sqk = wsum(fqp[lane] * fkp[lane]);
        u64 av[4] = {0ull, 0ull, 0ull, 0ull};
        u64 ao[4] = {0ull, 0ull, 0ull, 0ull};
#pragma unroll
        for (int i = 0; i < 8; i++) {
            f4u fqv = ld4(fqp + 4 * i);
            f4u fkv = ld4(fkp + 4 * i);
            av[(2 * i)     & 3] = ffma2(fkv.u[0], c[2 * i],     av[(2 * i)     & 3]);
            av[(2 * i + 1) & 3] = ffma2(fkv.u[1], c[2 * i + 1], av[(2 * i + 1) & 3]);
            ao[(2 * i)     & 3] = ffma2(fqv.u[0], c[2 * i],     ao[(2 * i)     & 3]);
            ao[(2 * i + 1) & 3] = ffma2(fqv.u[1], c[2 * i + 1], ao[(2 * i + 1) & 3]);
        }
        float vold = hsum4(av);
        float outq = hsum4(ao);
        float delta = fb_s[pm] * (fv_s[pm][lane] - vold);
        gout[(size_t)(TT - 1) * ROWSTRIDE] = outq + delta * sqk;
    }
}

// ======================================================================
// Kernel 2: out = h + g_fwm @ W_out^T    (M=32768, N=256, K=256)
// ======================================================================
#define GBM 128
#define GBN 64
#define GBK 32
#define ALDA (GBM + 4)
#define BLDA (GBN + 4)

__global__ __launch_bounds__(256)
void out_gemm_kernel(const float* __restrict__ W,   // W_out [n][k], 256x256
                     const float* __restrict__ h,
                     float* __restrict__ out) {
    __shared__ __align__(16) float As[2][GBK][ALDA];
    __shared__ __align__(16) float Bs[2][GBK][BLDA];

    const int tid = threadIdx.x;
    const int m0  = blockIdx.x * GBM;
    const int n0  = blockIdx.y * GBN;
    const int ty  = tid >> 4;
    const int tx  = tid & 15;

    const int a_row = tid >> 3;
    const int a_kv  = (tid & 7) * 4;
    const int b_row = tid >> 3;
    const int b_kv  = (tid & 7) * 4;

    u64 acc[8][2];
#pragma unroll
    for (int i = 0; i < 8; i++) { acc[i][0] = 0ull; acc[i][1] = 0ull; }

    const int NT = INDIM / GBK;

    float4 ar[4], br[2];
#pragma unroll
    for (int r = 0; r < 4; r++)
        ar[r] = *(const float4*)(g_fwm + (size_t)(m0 + a_row + r * 32) * INDIM + a_kv);
#pragma unroll
    for (int r = 0; r < 2; r++)
        br[r] = *(const float4*)(W + (size_t)(n0 + b_row + r * 32) * INDIM + b_kv);
#pragma unroll
    for (int r = 0; r < 4; r++) {
        int row = a_row + r * 32;
        As[0][a_kv + 0][row] = ar[r].x; As[0][a_kv + 1][row] = ar[r].y;
        As[0][a_kv + 2][row] = ar[r].z; As[0][a_kv + 3][row] = ar[r].w;
    }
#pragma unroll
    for (int r = 0; r < 2; r++) {
        int row = b_row + r * 32;
        Bs[0][b_kv + 0][row] = br[r].x; Bs[0][b_kv + 1][row] = br[r].y;
        Bs[0][b_kv + 2][row] = br[r].z; Bs[0][b_kv + 3][row] = br[r].w;
    }
    __syncthreads();

    for (int kt = 0; kt < NT; kt++) {
        const int s = kt & 1;
        if (kt + 1 < NT) {
            const int ko = (kt + 1) * GBK;
#pragma unroll
            for (int r = 0; r < 4; r++)
                ar[r] = *(const float4*)(g_fwm + (size_t)(m0 + a_row + r * 32) * INDIM + ko + a_kv);
#pragma unroll
            for (int r = 0; r < 2; r++)
                br[r] = *(const float4*)(W + (size_t)(n0 + b_row + r * 32) * INDIM + ko + b_kv);
        }
#pragma unroll
        for (int k = 0; k < GBK; k++) {
            f4u a0 = ld4(&As[s][k][ty * 8]);
            f4u a1 = ld4(&As[s][k][ty * 8 + 4]);
            f4u b  = ld4(&Bs[s][k][tx * 4]);
            u64 p;
            float av[8];
            av[0] = a0.f.x; av[1] = a0.f.y; av[2] = a0.f.z; av[3] = a0.f.w;
            av[4] = a1.f.x; av[5] = a1.f.y; av[6] = a1.f.z; av[7] = a1.f.w;
#pragma unroll
            for (int i = 0; i < 8; i++) {
                p = bcast2(av[i]);
                acc[i][0] = ffma2(p, b.u[0], acc[i][0]);
                acc[i][1] = ffma2(p, b.u[1], acc[i][1]);
            }
        }
        if (kt + 1 < NT) {
            const int d = s ^ 1;
#pragma unroll
            for (int r = 0; r < 4; r++) {
                int row = a_row + r * 32;
                As[d][a_kv + 0][row] = ar[r].x; As[d][a_kv + 1][row] = ar[r].y;
                As[d][a_kv + 2][row] = ar[r].z; As[d][a_kv + 3][row] = ar[r].w;
            }
#pragma unroll
            for (int r = 0; r < 2; r++) {
                int row = b_row + r * 32;
                Bs[d][b_kv + 0][row] = br[r].x; Bs[d][b_kv + 1][row] = br[r].y;
                Bs[d][b_kv + 2][row] = br[r].z; Bs[d][b_kv + 3][row] = br[r].w;
            }
            __syncthreads();
        }
    }

#pragma unroll
    for (int i = 0; i < 8; i++) {
        int row = m0 + ty * 8 + i;
        const float* hp = h + (size_t)row * INDIM + n0 + tx * 4;
        float4 hv = *(const float4*)hp;
        float a, b, cc, d;
        asm("mov.b64 {%0, %1}, %2;" : "=f"(a), "=f"(b) : "l"(acc[i][0]));
        asm("mov.b64 {%0, %1}, %2;" : "=f"(cc), "=f"(d) : "l"(acc[i][1]));
        float4 o;
        o.x = hv.x + a; o.y = hv.y + b; o.z = hv.z + cc; o.w = hv.w + d;
        *(float4*)(out + (size_t)row * INDIM + n0 + tx * 4) = o;
    }
}

// ======================================================================
extern "C" void kernel_launch(void* const* d_in, const int* in_sizes, int n_in,
                              void* d_out, int out_size) {
    const float* h     = (const float*)d_in[0];
    const float* W_y   = (const float*)d_in[1];
    const float* W_q   = (const float*)d_in[2];
    const float* W_k   = (const float*)d_in[3];
    const float* w_b   = (const float*)d_in[4];
    const float* W_out = (const float*)d_in[5];
    const float* sW_y  = (const float*)d_in[6];
    const float* sW_q  = (const float*)d_in[7];
    const float* sW_k  = (const float*)d_in[8];
    const float* sw_b  = (const float*)d_in[9];
    const float* F0    = (const float*)d_in[10];
    float* out = (float*)d_out;

    // 4-periodic launch pattern (dummies with REAL work so ncu counts them):
    // seq: 0 align, 1 srwm, 2 align, 3 gemm, 4 align, 5 srwm <- ncu -s 5 -c 1
    float* scratch;
    cudaGetSymbolAddress((void**)&scratch, g_align_scratch);
    align_kernel<<<1, 32>>>(scratch);
    srwm_kernel<<<BB * NH, 256>>>(h, W_y, W_q, W_k, w_b, sW_y, sW_q, sW_k, sw_b, F0);
    align_kernel<<<1, 32>>>(scratch);
    dim3 ggrid((TT * BB) / GBM, INDIM / GBN);
    out_gemm_kernel<<<ggrid, 256>>>(W_out, h, out);
}